// round 2
// baseline (speedup 1.0000x reference)
#include <cuda_runtime.h>

// Problem constants (from reference setup_inputs)
#define NB 4            // batch
#define EE 16           // embedding dims
#define HW 320000       // 400*800 pixels per image
#define NV (HW / 4)     // float4 groups per plane = 80000
#define CC 20           // label count
#define CK 19           // kept clusters (label 0 = IGNORE)
#define STR 17          // padded stride for [label][e] shared accumulators

// Scratch (no allocations allowed -> __device__ globals)
__device__ float g_sums[NB * CC * EE];
__device__ float g_cnt[NB * CC];
__device__ float g_means[NB * CC * EE];
__device__ float g_var[NB * CC];
__device__ float g_distreg[NB];

// ---------------------------------------------------------------------------
// Zero the accumulators (must run every call: graph replays require it)
// ---------------------------------------------------------------------------
__global__ void k_zero() {
    int i = threadIdx.x;
    for (int j = i; j < NB * CC * EE; j += blockDim.x) g_sums[j] = 0.f;
    for (int j = i; j < NB * CC; j += blockDim.x) { g_cnt[j] = 0.f; g_var[j] = 0.f; }
    if (i < NB) g_distreg[i] = 0.f;
}

// ---------------------------------------------------------------------------
// Pass 1: segment sums + counts per (batch, label, dim)
// Shared layout: 4 replicas (warp%4) of [CC][STR]; slot e<16 = sums, e==16 = count
// stride 17 keeps labels on distinct banks for a fixed e.
// ---------------------------------------------------------------------------
__global__ void __launch_bounds__(256) k_pass1(const float* __restrict__ emb,
                                               const int* __restrict__ tgt) {
    const int n = blockIdx.y;
    __shared__ float s[4][CC * STR];
    for (int j = threadIdx.x; j < 4 * CC * STR; j += blockDim.x)
        (&s[0][0])[j] = 0.f;
    __syncthreads();

    float* sr = s[(threadIdx.x >> 5) & 3];
    const float4* embn = reinterpret_cast<const float4*>(emb) + (size_t)n * EE * NV;
    const int4*   tgtn = reinterpret_cast<const int4*>(tgt) + (size_t)n * NV;

    for (int v = blockIdx.x * blockDim.x + threadIdx.x; v < NV;
         v += gridDim.x * blockDim.x) {
        int4 L = tgtn[v];
        int bx = L.x * STR, by = L.y * STR, bz = L.z * STR, bw = L.w * STR;
        atomicAdd(&sr[bx + 16], 1.f);
        atomicAdd(&sr[by + 16], 1.f);
        atomicAdd(&sr[bz + 16], 1.f);
        atomicAdd(&sr[bw + 16], 1.f);
#pragma unroll
        for (int e = 0; e < EE; e++) {
            float4 x = embn[(size_t)e * NV + v];
            atomicAdd(&sr[bx + e], x.x);
            atomicAdd(&sr[by + e], x.y);
            atomicAdd(&sr[bz + e], x.z);
            atomicAdd(&sr[bw + e], x.w);
        }
    }
    __syncthreads();

    for (int j = threadIdx.x; j < CC * STR; j += blockDim.x) {
        float vsum = s[0][j] + s[1][j] + s[2][j] + s[3][j];
        int lab = j / STR, e = j % STR;
        if (e < EE)
            atomicAdd(&g_sums[(n * CC + lab) * EE + e], vsum);
        else
            atomicAdd(&g_cnt[n * CC + lab], vsum);
    }
}

// ---------------------------------------------------------------------------
// Means + distance (push) term + regularizer. One block per batch.
// ---------------------------------------------------------------------------
__global__ void k_means() {
    const int n = blockIdx.x;
    __shared__ float m[CC * STR];
    __shared__ float cnt[CC];
    __shared__ float acc[2];
    const int tid = threadIdx.x;

    if (tid < 2) acc[tid] = 0.f;
    if (tid < CC) cnt[tid] = g_cnt[n * CC + tid];
    __syncthreads();

    for (int j = tid; j < CC * EE; j += blockDim.x) {
        int lab = j / EE, e = j % EE;
        float mv = g_sums[n * CC * EE + j] / cnt[lab];
        m[lab * STR + e] = mv;
        g_means[n * CC * EE + j] = mv;
    }
    __syncthreads();

    // push term over kept clusters (labels 1..19)
    float part = 0.f;
    for (int pr = tid; pr < CK * CK; pr += blockDim.x) {
        int i = pr / CK + 1, j2 = pr % CK + 1;
        if (i != j2) {
            float d2 = 0.f;
#pragma unroll
            for (int e = 0; e < EE; e++) {
                float df = m[i * STR + e] - m[j2 * STR + e];
                d2 += df * df;
            }
            float dm = (d2 > 0.f) ? sqrtf(d2) : 0.f;
            float h = fmaxf(3.0f - dm, 0.f);   // 2*DELTA_DIST = 3
            part += h * h;
        }
    }
    // regularizer: sum of ||mean_k||
    float reg = 0.f;
    for (int c = tid + 1; c < CC; c += blockDim.x) {
        float d2 = 0.f;
#pragma unroll
        for (int e = 0; e < EE; e++) {
            float mv = m[c * STR + e];
            d2 += mv * mv;
        }
        reg += (d2 > 0.f) ? sqrtf(d2) : 0.f;
    }
    atomicAdd(&acc[0], part);
    atomicAdd(&acc[1], reg);
    __syncthreads();
    if (tid == 0)
        g_distreg[n] = acc[0] / (float)(CK * (CK - 1)) + 0.001f * acc[1] / (float)CK;
}

// ---------------------------------------------------------------------------
// Pass 2: variance (pull) term. Per pixel: ||x - mean[lab]||, hinge^2, segment sum.
// ---------------------------------------------------------------------------
__global__ void __launch_bounds__(256) k_pass2(const float* __restrict__ emb,
                                               const int* __restrict__ tgt) {
    const int n = blockIdx.y;
    __shared__ float m[CC * STR];
    __shared__ float sv[CC];
    const int tid = threadIdx.x;

    for (int j = tid; j < CC * EE; j += blockDim.x) {
        int lab = j / EE, e = j % EE;
        m[lab * STR + e] = g_means[n * CC * EE + j];
    }
    if (tid < CC) sv[tid] = 0.f;
    __syncthreads();

    const float4* embn = reinterpret_cast<const float4*>(emb) + (size_t)n * EE * NV;
    const int4*   tgtn = reinterpret_cast<const int4*>(tgt) + (size_t)n * NV;

    for (int v = blockIdx.x * blockDim.x + tid; v < NV;
         v += gridDim.x * blockDim.x) {
        int4 L = tgtn[v];
        int bx = L.x * STR, by = L.y * STR, bz = L.z * STR, bw = L.w * STR;
        float d0 = 0.f, d1 = 0.f, d2 = 0.f, d3 = 0.f;
#pragma unroll
        for (int e = 0; e < EE; e++) {
            float4 x = embn[(size_t)e * NV + v];
            float t0 = x.x - m[bx + e]; d0 = fmaf(t0, t0, d0);
            float t1 = x.y - m[by + e]; d1 = fmaf(t1, t1, d1);
            float t2 = x.z - m[bz + e]; d2 = fmaf(t2, t2, d2);
            float t3 = x.w - m[bw + e]; d3 = fmaf(t3, t3, d3);
        }
        if (L.x != 0) { float d = sqrtf(d0); float h = fmaxf(d - 0.5f, 0.f); atomicAdd(&sv[L.x], h * h); }
        if (L.y != 0) { float d = sqrtf(d1); float h = fmaxf(d - 0.5f, 0.f); atomicAdd(&sv[L.y], h * h); }
        if (L.z != 0) { float d = sqrtf(d2); float h = fmaxf(d - 0.5f, 0.f); atomicAdd(&sv[L.z], h * h); }
        if (L.w != 0) { float d = sqrtf(d3); float h = fmaxf(d - 0.5f, 0.f); atomicAdd(&sv[L.w], h * h); }
    }
    __syncthreads();
    if (tid < CC) atomicAdd(&g_var[n * CC + tid], sv[tid]);
}

// ---------------------------------------------------------------------------
// Finalize: combine variance, distance, reg terms; mean over batches.
// ---------------------------------------------------------------------------
__global__ void k_final(float* __restrict__ out) {
    __shared__ float s[NB];
    const int tid = threadIdx.x;
    if (tid < NB) s[tid] = 0.f;
    __syncthreads();
    if (tid < NB * CK) {
        int n = tid / CK, c = tid % CK + 1;
        atomicAdd(&s[n], g_var[n * CC + c] / g_cnt[n * CC + c]);
    }
    __syncthreads();
    if (tid == 0) {
        float tot = 0.f;
        for (int n = 0; n < NB; n++)
            tot += s[n] / (float)CK + g_distreg[n];
        out[0] = tot / (float)NB;
    }
}

// ---------------------------------------------------------------------------
extern "C" void kernel_launch(void* const* d_in, const int* in_sizes, int n_in,
                              void* d_out, int out_size) {
    const float* emb = (const float*)d_in[0];
    const int*   tgt = (const int*)d_in[1];
    float*       out = (float*)d_out;

    k_zero<<<1, 256>>>();
    k_pass1<<<dim3(128, NB), 256>>>(emb, tgt);
    k_means<<<NB, 128>>>();
    k_pass2<<<dim3(128, NB), 256>>>(emb, tgt);
    k_final<<<1, 128>>>(out);
}